// round 5
// baseline (speedup 1.0000x reference)
#include <cuda_runtime.h>

#define NR 6144
typedef unsigned long long ull;

// ------------------------- scratch (device globals) -------------------------
__device__ float g_fe [2][NR*64];
__device__ float g_cs [2][64];
__device__ float g_x  [2][NR*64];
__device__ float g_q  [2][NR*64];
__device__ float g_k  [2][NR*64];
__device__ float g_v  [2][NR*64];
__device__ float g_kvp[2][48][512];
__device__ float g_M  [2][4096];
__device__ float g_emb[2][NR*64];
__device__ float g_comb[NR*64];
__device__ float g_u  [2][NR*64];

// ------------------------- helpers -------------------------
__device__ __forceinline__ float spikef(float x){
    float y = 4.0f * x;
    y = fminf(fmaxf(y, 0.0f), 4.0f);
    return floorf(y + 0.5f) * 0.25f;
}
__device__ __forceinline__ ull pack2(float lo, float hi){
    ull r;
    asm("mov.b64 %0, {%1, %2};" : "=l"(r) : "r"(__float_as_uint(lo)), "r"(__float_as_uint(hi)));
    return r;
}
__device__ __forceinline__ ull dup2(float x){ return pack2(x, x); }
__device__ __forceinline__ void ffma2(ull &d, ull a, ull b){
    asm("fma.rn.f32x2 %0, %1, %2, %0;" : "+l"(d) : "l"(a), "l"(b));
}
__device__ __forceinline__ void unpack2(ull v, float &lo, float &hi){
    unsigned a, b;
    asm("mov.b64 {%0, %1}, %2;" : "=r"(a), "=r"(b) : "l"(v));
    lo = __uint_as_float(a); hi = __uint_as_float(b);
}

// ------------------------- GEMM v2: 64x64 tile, 256 thr, BK=16, dbuf -------------------------
// C[6144, N] = post( A[6144,K] @ B[K,N] );  ldn = N = row stride of B and C.
// DUAL: A = w0*A0+w1*A1.  COLS: += cb*colsum[col].  ADDX: += X (ld 64).
// SPIKE: spike().  C2W: also write C2.  NB: N-tiled via blockIdx.y with bounds.
struct KA {
    const float* A0;
    const float* A1;
    const float* B;
    const float* X;
    float* C;
    float* C2;
    const float* cs;
    const float* cw;
    const float* cb;
    int K;
    int ldn;
};
struct KA6 { KA a[6]; };

#define BK 16

template<bool DUAL, bool SPIKE, bool ADDX, bool COLS, bool C2W, bool NB>
__global__ void __launch_bounds__(256, 3) gemm2(KA6 P){
    const KA a = P.a[blockIdx.z];
    const int tid = threadIdx.x;
    const int row0 = blockIdx.x * 64;
    const int n0 = NB ? blockIdx.y * 64 : 0;
    const int K = a.K;
    const int ldn = a.ldn;
    const int nt = (K + BK - 1) / BK;

    __shared__ float As[2][BK][68];
    __shared__ ull   Bs[2][BK][32];

    // global-load mapping
    const int arow = tid >> 2;            // 0..63
    const int akq  = (tid & 3) * 4;       // 0,4,8,12
    const int bk   = tid >> 4;            // 0..15
    const int bc   = (tid & 15) * 4;      // 0..60

    const float* Ap0 = a.A0 + (size_t)(row0 + arow) * K + akq;
    const float* Ap1 = DUAL ? (a.A1 + (size_t)(row0 + arow) * K + akq) : (const float*)0;
    const float* Bp  = a.B + (size_t)bk * ldn + n0 + bc;

    float w0 = 1.0f, w1 = 0.0f;
    if (DUAL){ w0 = a.cw[0]; w1 = a.cw[1]; }

    // compute mapping
    const int tx = tid & 15;              // row group: rows 4*tx..4*tx+3
    const int ty = tid >> 4;              // col group: cols 4*ty..4*ty+3

    ull acc[4][2];
    #pragma unroll
    for (int i = 0; i < 4; i++){ acc[i][0] = 0ull; acc[i][1] = 0ull; }

    float4 ra = make_float4(0.f,0.f,0.f,0.f);
    float4 ra1 = make_float4(0.f,0.f,0.f,0.f);
    float4 rb = make_float4(0.f,0.f,0.f,0.f);

    // load tile t into regs
    {
        const int k0 = 0;
        if (k0 + akq < K){
            ra = *(const float4*)(Ap0 + k0);
            if (DUAL) ra1 = *(const float4*)(Ap1 + k0);
        }
        bool inB = (k0 + bk < K) && (!NB || (n0 + bc < ldn));
        if (inB) rb = *(const float4*)(Bp + (size_t)k0 * ldn);
        else rb = make_float4(0.f,0.f,0.f,0.f);
    }
    // store tile 0
    {
        float x0 = ra.x, x1 = ra.y, x2 = ra.z, x3 = ra.w;
        if (DUAL){ x0 = w0*x0 + w1*ra1.x; x1 = w0*x1 + w1*ra1.y;
                   x2 = w0*x2 + w1*ra1.z; x3 = w0*x3 + w1*ra1.w; }
        As[0][akq+0][arow] = x0; As[0][akq+1][arow] = x1;
        As[0][akq+2][arow] = x2; As[0][akq+3][arow] = x3;
        Bs[0][bk][(tid&15)*2]   = pack2(rb.x, rb.y);
        Bs[0][bk][(tid&15)*2+1] = pack2(rb.z, rb.w);
    }
    __syncthreads();

    for (int t = 0; t < nt; t++){
        if (t + 1 < nt){
            const int k0 = (t + 1) * BK;
            if (k0 + akq < K){
                ra = *(const float4*)(Ap0 + k0);
                if (DUAL) ra1 = *(const float4*)(Ap1 + k0);
            } else {
                ra = make_float4(0.f,0.f,0.f,0.f);
                if (DUAL) ra1 = make_float4(0.f,0.f,0.f,0.f);
            }
            bool inB = (k0 + bk < K) && (!NB || (n0 + bc < ldn));
            rb = inB ? *(const float4*)(Bp + (size_t)k0 * ldn)
                     : make_float4(0.f,0.f,0.f,0.f);
        }
        const int buf = t & 1;
        #pragma unroll
        for (int k = 0; k < BK; k++){
            float4 a4 = *(const float4*)&As[buf][k][tx*4];
            ulonglong2 bb = *(const ulonglong2*)&Bs[buf][k][ty*2];
            ull b0 = bb.x, b1 = bb.y;
            ull d0 = dup2(a4.x), d1 = dup2(a4.y), d2 = dup2(a4.z), d3 = dup2(a4.w);
            ffma2(acc[0][0], d0, b0); ffma2(acc[0][1], d0, b1);
            ffma2(acc[1][0], d1, b0); ffma2(acc[1][1], d1, b1);
            ffma2(acc[2][0], d2, b0); ffma2(acc[2][1], d2, b1);
            ffma2(acc[3][0], d3, b0); ffma2(acc[3][1], d3, b1);
        }
        if (t + 1 < nt){
            const int nb = (t + 1) & 1;
            float x0 = ra.x, x1 = ra.y, x2 = ra.z, x3 = ra.w;
            if (DUAL){ x0 = w0*x0 + w1*ra1.x; x1 = w0*x1 + w1*ra1.y;
                       x2 = w0*x2 + w1*ra1.z; x3 = w0*x3 + w1*ra1.w; }
            As[nb][akq+0][arow] = x0; As[nb][akq+1][arow] = x1;
            As[nb][akq+2][arow] = x2; As[nb][akq+3][arow] = x3;
            Bs[nb][bk][(tid&15)*2]   = pack2(rb.x, rb.y);
            Bs[nb][bk][(tid&15)*2+1] = pack2(rb.z, rb.w);
            __syncthreads();
        }
    }

    // epilogue
    const int col = ty * 4;
    float cs0 = 0.f, cs1 = 0.f, cs2 = 0.f, cs3 = 0.f;
    if (COLS){
        float cb = a.cb[0];
        cs0 = cb * a.cs[col];   cs1 = cb * a.cs[col+1];
        cs2 = cb * a.cs[col+2]; cs3 = cb * a.cs[col+3];
    }
    bool colok = (!NB) || (n0 + col < ldn);
    #pragma unroll
    for (int i = 0; i < 4; i++){
        int r = row0 + tx*4 + i;
        float v0, v1, v2, v3;
        unpack2(acc[i][0], v0, v1);
        unpack2(acc[i][1], v2, v3);
        if (COLS){ v0 += cs0; v1 += cs1; v2 += cs2; v3 += cs3; }
        if (ADDX){
            const float* xr = a.X + (size_t)r*64 + col;
            v0 += xr[0]; v1 += xr[1]; v2 += xr[2]; v3 += xr[3];
        }
        if (SPIKE){ v0 = spikef(v0); v1 = spikef(v1); v2 = spikef(v2); v3 = spikef(v3); }
        if (colok){
            *(float4*)(a.C + (size_t)r*ldn + n0 + col) = make_float4(v0, v1, v2, v3);
            if (C2W)
                *(float4*)(a.C2 + (size_t)r*ldn + n0 + col) = make_float4(v0, v1, v2, v3);
        }
    }
}

// ------------------------- column sums of fe -------------------------
__global__ void __launch_bounds__(256) colsum_kernel(){
    int c = blockIdx.x, om = blockIdx.y;
    float s = 0.f;
    for (int r = threadIdx.x; r < NR; r += 256) s += g_fe[om][(size_t)r*64 + c];
    __shared__ float red[256];
    red[threadIdx.x] = s;
    __syncthreads();
    for (int o = 128; o > 0; o >>= 1){
        if (threadIdx.x < o) red[threadIdx.x] += red[threadIdx.x + o];
        __syncthreads();
    }
    if (threadIdx.x == 0) g_cs[om][c] = red[0];
}

// ------------------------- partial kv = sum_n k[n,h,d] v[n,h,e] -------------------------
__global__ void __launch_bounds__(512) kvpart_kernel(){
    int om = blockIdx.y, bx = blockIdx.x;
    int tid = threadIdx.x;
    int h = tid >> 6, d = (tid >> 3) & 7, e = tid & 7;
    __shared__ float ks[8][64], vs[8][64];
    int r0 = bx * 128;
    int lr = tid >> 6, lc = tid & 63;
    float acc = 0.f;
    for (int c = 0; c < 16; c++){
        ks[lr][lc] = g_k[om][(size_t)(r0 + c*8 + lr)*64 + lc];
        vs[lr][lc] = g_v[om][(size_t)(r0 + c*8 + lr)*64 + lc];
        __syncthreads();
        #pragma unroll
        for (int n = 0; n < 8; n++)
            acc += ks[n][h*8 + d] * vs[n][h*8 + e];
        __syncthreads();
    }
    g_kvp[om][bx][tid] = acc;
}

// ------------------------- reduce kv, build M[hd,c] = 0.25 * sum_e kv[h,d,e] wp[he,c] ------
__global__ void __launch_bounds__(512) kvm_kernel(const float* wp0, const float* wp1){
    int om = blockIdx.x;
    const float* wp = om ? wp1 : wp0;
    int tid = threadIdx.x;
    __shared__ float kvs[512];
    float s = 0.f;
    for (int b = 0; b < 48; b++) s += g_kvp[om][b][tid];
    kvs[tid] = s;
    __syncthreads();
    #pragma unroll
    for (int i = 0; i < 8; i++){
        int idx = tid + i*512;
        int hd = idx >> 6, c = idx & 63;
        int h = hd >> 3, dd = hd & 7;
        float m = 0.f;
        #pragma unroll
        for (int e = 0; e < 8; e++)
            m += kvs[h*64 + dd*8 + e] * wp[(h*8 + e)*64 + c];
        g_M[om][idx] = 0.25f * m;
    }
}

// ------------------------- fused MLP -------------------------
__global__ void __launch_bounds__(256) fc_kernel(const float* fc1w, const float* fc1b,
                                                 const float* fc2w, const float* fc2b,
                                                 float* out3){
    __shared__ float cat_s[64][129];
    int tid = threadIdx.x;
    int row0 = blockIdx.x * 64;
    int tx = tid & 15, ty = tid >> 4;

    for (int i = tid; i < 64*128; i += 256){
        int row = i >> 7, k = i & 127;
        float v = (k < 64) ? g_emb[0][(size_t)(row0+row)*64 + k]
                           : g_emb[1][(size_t)(row0+row)*64 + (k - 64)];
        cat_s[row][k] = v;
    }
    __syncthreads();

    float acc[4][4];
    #pragma unroll
    for (int i = 0; i < 4; i++)
        #pragma unroll
        for (int j = 0; j < 4; j++) acc[i][j] = 0.f;

    for (int k = 0; k < 128; k++){
        float aa[4], bb[4];
        #pragma unroll
        for (int i = 0; i < 4; i++) aa[i] = cat_s[tx*4 + i][k];
        #pragma unroll
        for (int j = 0; j < 4; j++) bb[j] = fc1w[k*64 + ty*4 + j];
        #pragma unroll
        for (int i = 0; i < 4; i++)
            #pragma unroll
            for (int j = 0; j < 4; j++) acc[i][j] += aa[i]*bb[j];
    }
    __syncthreads();
    #pragma unroll
    for (int i = 0; i < 4; i++)
        #pragma unroll
        for (int j = 0; j < 4; j++)
            cat_s[tx*4 + i][ty*4 + j] = spikef(acc[i][j] + fc1b[ty*4 + j]);
    __syncthreads();

    float acc2[4][4];
    #pragma unroll
    for (int i = 0; i < 4; i++)
        #pragma unroll
        for (int j = 0; j < 4; j++) acc2[i][j] = 0.f;
    for (int k = 0; k < 64; k++){
        float aa[4], bb[4];
        #pragma unroll
        for (int i = 0; i < 4; i++) aa[i] = cat_s[tx*4 + i][k];
        #pragma unroll
        for (int j = 0; j < 4; j++) bb[j] = fc2w[k*64 + ty*4 + j];
        #pragma unroll
        for (int i = 0; i < 4; i++)
            #pragma unroll
            for (int j = 0; j < 4; j++) acc2[i][j] += aa[i]*bb[j];
    }
    #pragma unroll
    for (int i = 0; i < 4; i++)
        #pragma unroll
        for (int j = 0; j < 4; j++){
            int r = row0 + tx*4 + i, c = ty*4 + j;
            float v = acc2[i][j] + fc2b[c];
            g_comb[(size_t)r*64 + c] = v;
            out3[(size_t)r*64 + c]   = spikef(v);
        }
}

// ------------------------- launch -------------------------
static inline KA mkKA(const float* A0, const float* A1, const float* B, const float* X,
                      float* C, float* C2, const float* cs, const float* cw,
                      const float* cb, int K, int ldn){
    KA a; a.A0=A0; a.A1=A1; a.B=B; a.X=X; a.C=C; a.C2=C2;
    a.cs=cs; a.cw=cw; a.cb=cb; a.K=K; a.ldn=ldn; return a;
}

extern "C" void kernel_launch(void* const* d_in, const int* in_sizes, int n_in,
                              void* d_out, int out_size){
    const float* feat1 = (const float*)d_in[0];
    const float* feat2 = (const float*)d_in[1];
    const float* AS1   = (const float*)d_in[2];
    const float* AF1   = (const float*)d_in[3];
    const float* AS2   = (const float*)d_in[4];
    const float* AF2   = (const float*)d_in[5];
    const float* c1w   = (const float*)d_in[6];
    const float* c1b   = (const float*)d_in[7];
    const float* c2w   = (const float*)d_in[8];
    const float* c2b   = (const float*)d_in[9];
    const float* wenc1 = (const float*)d_in[10];
    const float* wq1   = (const float*)d_in[11];
    const float* wk1   = (const float*)d_in[12];
    const float* wv1   = (const float*)d_in[13];
    const float* wp1   = (const float*)d_in[14];
    const float* wenc2 = (const float*)d_in[15];
    const float* wq2   = (const float*)d_in[16];
    const float* wk2   = (const float*)d_in[17];
    const float* wv2   = (const float*)d_in[18];
    const float* wp2   = (const float*)d_in[19];
    const float* fc1w  = (const float*)d_in[20];
    const float* fc1b  = (const float*)d_in[21];
    const float* fc2w  = (const float*)d_in[22];
    const float* fc2b  = (const float*)d_in[23];
    const float* wdec1 = (const float*)d_in[24];
    const float* wdec2 = (const float*)d_in[25];
    float* out = (float*)d_out;

    float *p_fe, *p_cs, *p_x, *p_q, *p_k, *p_v, *p_M, *p_emb, *p_comb, *p_u;
    cudaGetSymbolAddress((void**)&p_fe,  g_fe);
    cudaGetSymbolAddress((void**)&p_cs,  g_cs);
    cudaGetSymbolAddress((void**)&p_x,   g_x);
    cudaGetSymbolAddress((void**)&p_q,   g_q);
    cudaGetSymbolAddress((void**)&p_k,   g_k);
    cudaGetSymbolAddress((void**)&p_v,   g_v);
    cudaGetSymbolAddress((void**)&p_M,   g_M);
    cudaGetSymbolAddress((void**)&p_emb, g_emb);
    cudaGetSymbolAddress((void**)&p_comb,g_comb);
    cudaGetSymbolAddress((void**)&p_u,   g_u);
    const int OFF = NR*64;

    KA6 P;

    // 1. fe = feat @ w_enc            (grid z: omics)
    P.a[0] = mkKA(feat1, 0, wenc1, 0, p_fe,       0, 0, 0, 0, 3000, 64);
    P.a[1] = mkKA(feat2, 0, wenc2, 0, p_fe + OFF, 0, 0, 0, 0, 512,  64);
    for (int i = 2; i < 6; i++) P.a[i] = P.a[0];
    gemm2<false,false,false,false,false,false><<<dim3(96,1,2), 256>>>(P);

    // 2. column sums of fe
    colsum_kernel<<<dim3(64, 2), 256>>>();

    // 3. x = spike((w0*AS + w1*AF) @ fe + cb*colsum)
    P.a[0] = mkKA(AS1, AF1, p_fe,       0, p_x,       0, p_cs,      c1w, c1b, NR, 64);
    P.a[1] = mkKA(AS2, AF2, p_fe + OFF, 0, p_x + OFF, 0, p_cs + 64, c2w, c2b, NR, 64);
    for (int i = 2; i < 6; i++) P.a[i] = P.a[0];
    gemm2<true,true,false,true,false,false><<<dim3(96,1,2), 256>>>(P);

    // 4. q,k,v = spike(x @ w)  — all six in one launch (grid z = 6)
    P.a[0] = mkKA(p_x,       0, wq1, 0, p_q,       0, 0, 0, 0, 64, 64);
    P.a[1] = mkKA(p_x + OFF, 0, wq2, 0, p_q + OFF, 0, 0, 0, 0, 64, 64);
    P.a[2] = mkKA(p_x,       0, wk1, 0, p_k,       0, 0, 0, 0, 64, 64);
    P.a[3] = mkKA(p_x + OFF, 0, wk2, 0, p_k + OFF, 0, 0, 0, 0, 64, 64);
    P.a[4] = mkKA(p_x,       0, wv1, 0, p_v,       0, 0, 0, 0, 64, 64);
    P.a[5] = mkKA(p_x + OFF, 0, wv2, 0, p_v + OFF, 0, 0, 0, 0, 64, 64);
    gemm2<false,true,false,false,false,false><<<dim3(96,1,6), 256>>>(P);

    // 5-6. kv partials, reduce + fold wp into M
    kvpart_kernel<<<dim3(48, 2), 512>>>();
    kvm_kernel<<<2, 512>>>(wp1, wp2);

    // 7. emb = x + q @ M   (writes g_emb and emb1/emb2 output regions)
    P.a[0] = mkKA(p_q,       0, p_M,        p_x,       p_emb,       out,       0,0,0, 64, 64);
    P.a[1] = mkKA(p_q + OFF, 0, p_M + 4096, p_x + OFF, p_emb + OFF, out + OFF, 0,0,0, 64, 64);
    for (int i = 2; i < 6; i++) P.a[i] = P.a[0];
    gemm2<false,false,true,false,true,false><<<dim3(96,1,2), 256>>>(P);

    // 8. MLP
    fc_kernel<<<96, 256>>>(fc1w, fc1b, fc2w, fc2b, out + 2*OFF);

    // 9. u = AS @ comb
    P.a[0] = mkKA(AS1, 0, p_comb, 0, p_u,       0, 0, 0, 0, NR, 64);
    P.a[1] = mkKA(AS2, 0, p_comb, 0, p_u + OFF, 0, 0, 0, 0, NR, 64);
    for (int i = 2; i < 6; i++) P.a[i] = P.a[0];
    gemm2<false,false,false,false,false,false><<<dim3(96,1,2), 256>>>(P);

    // 10. recon = spike(u @ w_dec)  (N-tiled)
    P.a[0] = mkKA(p_u, 0, wdec1, 0, out + 3*(size_t)OFF, 0, 0, 0, 0, 64, 3000);
    for (int i = 1; i < 6; i++) P.a[i] = P.a[0];
    gemm2<false,true,false,false,false,true><<<dim3(96,47,1), 256>>>(P);

    P.a[0] = mkKA(p_u + OFF, 0, wdec2, 0, out + 3*(size_t)OFF + (size_t)NR*3000,
                  0, 0, 0, 0, 64, 512);
    for (int i = 1; i < 6; i++) P.a[i] = P.a[0];
    gemm2<false,true,false,false,false,true><<<dim3(96,8,1), 256>>>(P);
}

// round 6
// speedup vs baseline: 1.2453x; 1.2453x over previous
#include <cuda_runtime.h>

#define NR 6144
typedef unsigned long long ull;

// ------------------------- scratch (device globals) -------------------------
__device__ float g_fe [2][NR*64];
__device__ float g_cs [2][64];
__device__ float g_x  [2][NR*64];
__device__ float g_q  [2][NR*64];
__device__ float g_k  [2][NR*64];
__device__ float g_v  [2][NR*64];
__device__ float g_kvp[2][48][512];
__device__ float g_M  [2][4096];
__device__ float g_emb[2][NR*64];
__device__ float g_comb[NR*64];
__device__ float g_u  [2][NR*64];

// ------------------------- helpers -------------------------
__device__ __forceinline__ float spikef(float x){
    float y = 4.0f * x;
    y = fminf(fmaxf(y, 0.0f), 4.0f);
    return floorf(y + 0.5f) * 0.25f;
}
__device__ __forceinline__ ull pack2(float lo, float hi){
    ull r;
    asm("mov.b64 %0, {%1, %2};" : "=l"(r) : "r"(__float_as_uint(lo)), "r"(__float_as_uint(hi)));
    return r;
}
__device__ __forceinline__ ull dup2(float x){ return pack2(x, x); }
__device__ __forceinline__ void ffma2(ull &d, ull a, ull b){
    asm("fma.rn.f32x2 %0, %1, %2, %0;" : "+l"(d) : "l"(a), "l"(b));
}
__device__ __forceinline__ void unpack2(ull v, float &lo, float &hi){
    unsigned a, b;
    asm("mov.b64 {%0, %1}, %2;" : "=r"(a), "=r"(b) : "l"(v));
    lo = __uint_as_float(a); hi = __uint_as_float(b);
}

// ------------------------- GEMM v3: 32x64 tile, 128 thr, BK=16, dbuf, 1 sync/iter ---------
// C[6144, N] = post( A[6144,K] @ B[K,N] );  ldn = row stride of B and C.
// DUAL: A = w0*A0+w1*A1.  COLS: += cb*colsum[col].  ADDX: += X (ld 64).
// SPIKE: spike().  C2W: also write C2.  NB: N-tiled via blockIdx.y with bounds.
struct KA {
    const float* A0;
    const float* A1;
    const float* B;
    const float* X;
    float* C;
    float* C2;
    const float* cs;
    const float* cw;
    const float* cb;
    int K;
    int ldn;
};
struct KA6 { KA a[6]; };

#define BK 16

template<bool DUAL, bool SPIKE, bool ADDX, bool COLS, bool C2W, bool NB>
__global__ void __launch_bounds__(128, 6) gemm3(KA6 P){
    const KA a = P.a[blockIdx.z];
    const int tid = threadIdx.x;
    const int row0 = blockIdx.x * 32;
    const int n0 = NB ? blockIdx.y * 64 : 0;
    const int K = a.K;
    const int ldn = a.ldn;
    const int nt = (K + BK - 1) / BK;

    __shared__ float As[2][BK][36];
    __shared__ ull   Bs[2][BK][32];

    // global-load mapping
    const int arow = tid >> 2;            // 0..31
    const int akq  = (tid & 3) * 4;       // 0,4,8,12
    const int bk0  = tid >> 4;            // 0..7  (rows bk0, bk0+8)
    const int bc   = (tid & 15) * 4;      // 0..60

    const float* Ap0 = a.A0 + (size_t)(row0 + arow) * K + akq;
    const float* Ap1 = DUAL ? (a.A1 + (size_t)(row0 + arow) * K + akq) : (const float*)0;
    const float* Bp  = a.B + (size_t)bk0 * ldn + n0 + bc;

    float w0 = 1.0f, w1 = 0.0f;
    if (DUAL){ w0 = a.cw[0]; w1 = a.cw[1]; }

    // compute mapping: 4x4 per thread
    const int tx = tid & 7;               // rows 4*tx..4*tx+3
    const int ty = tid >> 3;              // cols 4*ty..4*ty+3

    ull acc[4][2];
    #pragma unroll
    for (int i = 0; i < 4; i++){ acc[i][0] = 0ull; acc[i][1] = 0ull; }

    float4 ra  = make_float4(0.f,0.f,0.f,0.f);
    float4 ra1 = make_float4(0.f,0.f,0.f,0.f);
    float4 rb0 = make_float4(0.f,0.f,0.f,0.f);
    float4 rb1 = make_float4(0.f,0.f,0.f,0.f);

    const bool ncol_ok = (!NB) || (n0 + bc < ldn);

    // prefetch tile 0
    {
        if (akq < K){
            ra = *(const float4*)(Ap0);
            if (DUAL) ra1 = *(const float4*)(Ap1);
        }
        if (ncol_ok){
            if (bk0 < K)     rb0 = *(const float4*)(Bp);
            if (bk0 + 8 < K) rb1 = *(const float4*)(Bp + (size_t)8 * ldn);
        }
    }
    // store tile 0
    {
        float x0 = ra.x, x1 = ra.y, x2 = ra.z, x3 = ra.w;
        if (DUAL){ x0 = w0*x0 + w1*ra1.x; x1 = w0*x1 + w1*ra1.y;
                   x2 = w0*x2 + w1*ra1.z; x3 = w0*x3 + w1*ra1.w; }
        As[0][akq+0][arow] = x0; As[0][akq+1][arow] = x1;
        As[0][akq+2][arow] = x2; As[0][akq+3][arow] = x3;
        const int c2 = (tid & 15) * 2;
        Bs[0][bk0][c2]       = pack2(rb0.x, rb0.y);
        Bs[0][bk0][c2+1]     = pack2(rb0.z, rb0.w);
        Bs[0][bk0+8][c2]     = pack2(rb1.x, rb1.y);
        Bs[0][bk0+8][c2+1]   = pack2(rb1.z, rb1.w);
    }
    __syncthreads();

    for (int t = 0; t < nt; t++){
        if (t + 1 < nt){
            const int k0 = (t + 1) * BK;
            if (k0 + akq < K){
                ra = *(const float4*)(Ap0 + k0);
                if (DUAL) ra1 = *(const float4*)(Ap1 + k0);
            } else {
                ra = make_float4(0.f,0.f,0.f,0.f);
                if (DUAL) ra1 = make_float4(0.f,0.f,0.f,0.f);
            }
            rb0 = make_float4(0.f,0.f,0.f,0.f);
            rb1 = make_float4(0.f,0.f,0.f,0.f);
            if (ncol_ok){
                if (k0 + bk0 < K)     rb0 = *(const float4*)(Bp + (size_t)k0 * ldn);
                if (k0 + bk0 + 8 < K) rb1 = *(const float4*)(Bp + (size_t)(k0 + 8) * ldn);
            }
        }
        const int buf = t & 1;
        #pragma unroll
        for (int k = 0; k < BK; k++){
            float4 a4 = *(const float4*)&As[buf][k][tx*4];
            ulonglong2 bb = *(const ulonglong2*)&Bs[buf][k][ty*2];
            ull b0 = bb.x, b1 = bb.y;
            ull d0 = dup2(a4.x), d1 = dup2(a4.y), d2 = dup2(a4.z), d3 = dup2(a4.w);
            ffma2(acc[0][0], d0, b0); ffma2(acc[0][1], d0, b1);
            ffma2(acc[1][0], d1, b0); ffma2(acc[1][1], d1, b1);
            ffma2(acc[2][0], d2, b0); ffma2(acc[2][1], d2, b1);
            ffma2(acc[3][0], d3, b0); ffma2(acc[3][1], d3, b1);
        }
        if (t + 1 < nt){
            const int nb = (t + 1) & 1;
            float x0 = ra.x, x1 = ra.y, x2 = ra.z, x3 = ra.w;
            if (DUAL){ x0 = w0*x0 + w1*ra1.x; x1 = w0*x1 + w1*ra1.y;
                       x2 = w0*x2 + w1*ra1.z; x3 = w0*x3 + w1*ra1.w; }
            As[nb][akq+0][arow] = x0; As[nb][akq+1][arow] = x1;
            As[nb][akq+2][arow] = x2; As[nb][akq+3][arow] = x3;
            const int c2 = (tid & 15) * 2;
            Bs[nb][bk0][c2]     = pack2(rb0.x, rb0.y);
            Bs[nb][bk0][c2+1]   = pack2(rb0.z, rb0.w);
            Bs[nb][bk0+8][c2]   = pack2(rb1.x, rb1.y);
            Bs[nb][bk0+8][c2+1] = pack2(rb1.z, rb1.w);
            __syncthreads();
        }
    }

    // epilogue
    const int col = ty * 4;
    float cs0 = 0.f, cs1 = 0.f, cs2 = 0.f, cs3 = 0.f;
    if (COLS){
        float cb = a.cb[0];
        cs0 = cb * a.cs[col];   cs1 = cb * a.cs[col+1];
        cs2 = cb * a.cs[col+2]; cs3 = cb * a.cs[col+3];
    }
    const bool colok = (!NB) || (n0 + col < ldn);
    #pragma unroll
    for (int i = 0; i < 4; i++){
        int r = row0 + tx*4 + i;
        float v0, v1, v2, v3;
        unpack2(acc[i][0], v0, v1);
        unpack2(acc[i][1], v2, v3);
        if (COLS){ v0 += cs0; v1 += cs1; v2 += cs2; v3 += cs3; }
        if (ADDX){
            const float* xr = a.X + (size_t)r*64 + col;
            v0 += xr[0]; v1 += xr[1]; v2 += xr[2]; v3 += xr[3];
        }
        if (SPIKE){ v0 = spikef(v0); v1 = spikef(v1); v2 = spikef(v2); v3 = spikef(v3); }
        if (colok){
            *(float4*)(a.C + (size_t)r*ldn + n0 + col) = make_float4(v0, v1, v2, v3);
            if (C2W)
                *(float4*)(a.C2 + (size_t)r*ldn + n0 + col) = make_float4(v0, v1, v2, v3);
        }
    }
}

// ------------------------- column sums of fe -------------------------
__global__ void __launch_bounds__(256) colsum_kernel(){
    int c = blockIdx.x, om = blockIdx.y;
    float s = 0.f;
    for (int r = threadIdx.x; r < NR; r += 256) s += g_fe[om][(size_t)r*64 + c];
    __shared__ float red[256];
    red[threadIdx.x] = s;
    __syncthreads();
    for (int o = 128; o > 0; o >>= 1){
        if (threadIdx.x < o) red[threadIdx.x] += red[threadIdx.x + o];
        __syncthreads();
    }
    if (threadIdx.x == 0) g_cs[om][c] = red[0];
}

// ------------------------- partial kv = sum_n k[n,h,d] v[n,h,e] -------------------------
__global__ void __launch_bounds__(512) kvpart_kernel(){
    int om = blockIdx.y, bx = blockIdx.x;
    int tid = threadIdx.x;
    int h = tid >> 6, d = (tid >> 3) & 7, e = tid & 7;
    __shared__ float ks[8][64], vs[8][64];
    int r0 = bx * 128;
    int lr = tid >> 6, lc = tid & 63;
    float acc = 0.f;
    for (int c = 0; c < 16; c++){
        ks[lr][lc] = g_k[om][(size_t)(r0 + c*8 + lr)*64 + lc];
        vs[lr][lc] = g_v[om][(size_t)(r0 + c*8 + lr)*64 + lc];
        __syncthreads();
        #pragma unroll
        for (int n = 0; n < 8; n++)
            acc += ks[n][h*8 + d] * vs[n][h*8 + e];
        __syncthreads();
    }
    g_kvp[om][bx][tid] = acc;
}

// ------------------------- reduce kv, build M[hd,c] = 0.25 * sum_e kv[h,d,e] wp[he,c] ------
__global__ void __launch_bounds__(512) kvm_kernel(const float* wp0, const float* wp1){
    int om = blockIdx.x;
    const float* wp = om ? wp1 : wp0;
    int tid = threadIdx.x;
    __shared__ float kvs[512];
    float s = 0.f;
    for (int b = 0; b < 48; b++) s += g_kvp[om][b][tid];
    kvs[tid] = s;
    __syncthreads();
    #pragma unroll
    for (int i = 0; i < 8; i++){
        int idx = tid + i*512;
        int hd = idx >> 6, c = idx & 63;
        int h = hd >> 3, dd = hd & 7;
        float m = 0.f;
        #pragma unroll
        for (int e = 0; e < 8; e++)
            m += kvs[h*64 + dd*8 + e] * wp[(h*8 + e)*64 + c];
        g_M[om][idx] = 0.25f * m;
    }
}

// ------------------------- fused MLP -------------------------
__global__ void __launch_bounds__(256) fc_kernel(const float* fc1w, const float* fc1b,
                                                 const float* fc2w, const float* fc2b,
                                                 float* out3){
    __shared__ float cat_s[64][129];
    int tid = threadIdx.x;
    int row0 = blockIdx.x * 64;
    int tx = tid & 15, ty = tid >> 4;

    for (int i = tid; i < 64*128; i += 256){
        int row = i >> 7, k = i & 127;
        float v = (k < 64) ? g_emb[0][(size_t)(row0+row)*64 + k]
                           : g_emb[1][(size_t)(row0+row)*64 + (k - 64)];
        cat_s[row][k] = v;
    }
    __syncthreads();

    float acc[4][4];
    #pragma unroll
    for (int i = 0; i < 4; i++)
        #pragma unroll
        for (int j = 0; j < 4; j++) acc[i][j] = 0.f;

    for (int k = 0; k < 128; k++){
        float aa[4], bb[4];
        #pragma unroll
        for (int i = 0; i < 4; i++) aa[i] = cat_s[tx*4 + i][k];
        #pragma unroll
        for (int j = 0; j < 4; j++) bb[j] = fc1w[k*64 + ty*4 + j];
        #pragma unroll
        for (int i = 0; i < 4; i++)
            #pragma unroll
            for (int j = 0; j < 4; j++) acc[i][j] += aa[i]*bb[j];
    }
    __syncthreads();
    #pragma unroll
    for (int i = 0; i < 4; i++)
        #pragma unroll
        for (int j = 0; j < 4; j++)
            cat_s[tx*4 + i][ty*4 + j] = spikef(acc[i][j] + fc1b[ty*4 + j]);
    __syncthreads();

    float acc2[4][4];
    #pragma unroll
    for (int i = 0; i < 4; i++)
        #pragma unroll
        for (int j = 0; j < 4; j++) acc2[i][j] = 0.f;
    for (int k = 0; k < 64; k++){
        float aa[4], bb[4];
        #pragma unroll
        for (int i = 0; i < 4; i++) aa[i] = cat_s[tx*4 + i][k];
        #pragma unroll
        for (int j = 0; j < 4; j++) bb[j] = fc2w[k*64 + ty*4 + j];
        #pragma unroll
        for (int i = 0; i < 4; i++)
            #pragma unroll
            for (int j = 0; j < 4; j++) acc2[i][j] += aa[i]*bb[j];
    }
    #pragma unroll
    for (int i = 0; i < 4; i++)
        #pragma unroll
        for (int j = 0; j < 4; j++){
            int r = row0 + tx*4 + i, c = ty*4 + j;
            float v = acc2[i][j] + fc2b[c];
            g_comb[(size_t)r*64 + c] = v;
            out3[(size_t)r*64 + c]   = spikef(v);
        }
}

// ------------------------- launch -------------------------
static inline KA mkKA(const float* A0, const float* A1, const float* B, const float* X,
                      float* C, float* C2, const float* cs, const float* cw,
                      const float* cb, int K, int ldn){
    KA a; a.A0=A0; a.A1=A1; a.B=B; a.X=X; a.C=C; a.C2=C2;
    a.cs=cs; a.cw=cw; a.cb=cb; a.K=K; a.ldn=ldn; return a;
}

extern "C" void kernel_launch(void* const* d_in, const int* in_sizes, int n_in,
                              void* d_out, int out_size){
    const float* feat1 = (const float*)d_in[0];
    const float* feat2 = (const float*)d_in[1];
    const float* AS1   = (const float*)d_in[2];
    const float* AF1   = (const float*)d_in[3];
    const float* AS2   = (const float*)d_in[4];
    const float* AF2   = (const float*)d_in[5];
    const float* c1w   = (const float*)d_in[6];
    const float* c1b   = (const float*)d_in[7];
    const float* c2w   = (const float*)d_in[8];
    const float* c2b   = (const float*)d_in[9];
    const float* wenc1 = (const float*)d_in[10];
    const float* wq1   = (const float*)d_in[11];
    const float* wk1   = (const float*)d_in[12];
    const float* wv1   = (const float*)d_in[13];
    const float* wp1   = (const float*)d_in[14];
    const float* wenc2 = (const float*)d_in[15];
    const float* wq2   = (const float*)d_in[16];
    const float* wk2   = (const float*)d_in[17];
    const float* wv2   = (const float*)d_in[18];
    const float* wp2   = (const float*)d_in[19];
    const float* fc1w  = (const float*)d_in[20];
    const float* fc1b  = (const float*)d_in[21];
    const float* fc2w  = (const float*)d_in[22];
    const float* fc2b  = (const float*)d_in[23];
    const float* wdec1 = (const float*)d_in[24];
    const float* wdec2 = (const float*)d_in[25];
    float* out = (float*)d_out;

    float *p_fe, *p_cs, *p_x, *p_q, *p_k, *p_v, *p_M, *p_emb, *p_comb, *p_u;
    cudaGetSymbolAddress((void**)&p_fe,  g_fe);
    cudaGetSymbolAddress((void**)&p_cs,  g_cs);
    cudaGetSymbolAddress((void**)&p_x,   g_x);
    cudaGetSymbolAddress((void**)&p_q,   g_q);
    cudaGetSymbolAddress((void**)&p_k,   g_k);
    cudaGetSymbolAddress((void**)&p_v,   g_v);
    cudaGetSymbolAddress((void**)&p_M,   g_M);
    cudaGetSymbolAddress((void**)&p_emb, g_emb);
    cudaGetSymbolAddress((void**)&p_comb,g_comb);
    cudaGetSymbolAddress((void**)&p_u,   g_u);
    const int OFF = NR*64;

    KA6 P;

    // 1. fe = feat @ w_enc            (grid z: omics)
    P.a[0] = mkKA(feat1, 0, wenc1, 0, p_fe,       0, 0, 0, 0, 3000, 64);
    P.a[1] = mkKA(feat2, 0, wenc2, 0, p_fe + OFF, 0, 0, 0, 0, 512,  64);
    for (int i = 2; i < 6; i++) P.a[i] = P.a[0];
    gemm3<false,false,false,false,false,false><<<dim3(192,1,2), 128>>>(P);

    // 2. column sums of fe
    colsum_kernel<<<dim3(64, 2), 256>>>();

    // 3. x = spike((w0*AS + w1*AF) @ fe + cb*colsum)
    P.a[0] = mkKA(AS1, AF1, p_fe,       0, p_x,       0, p_cs,      c1w, c1b, NR, 64);
    P.a[1] = mkKA(AS2, AF2, p_fe + OFF, 0, p_x + OFF, 0, p_cs + 64, c2w, c2b, NR, 64);
    for (int i = 2; i < 6; i++) P.a[i] = P.a[0];
    gemm3<true,true,false,true,false,false><<<dim3(192,1,2), 128>>>(P);

    // 4. q,k,v = spike(x @ w)  — all six in one launch (grid z = 6)
    P.a[0] = mkKA(p_x,       0, wq1, 0, p_q,       0, 0, 0, 0, 64, 64);
    P.a[1] = mkKA(p_x + OFF, 0, wq2, 0, p_q + OFF, 0, 0, 0, 0, 64, 64);
    P.a[2] = mkKA(p_x,       0, wk1, 0, p_k,       0, 0, 0, 0, 64, 64);
    P.a[3] = mkKA(p_x + OFF, 0, wk2, 0, p_k + OFF, 0, 0, 0, 0, 64, 64);
    P.a[4] = mkKA(p_x,       0, wv1, 0, p_v,       0, 0, 0, 0, 64, 64);
    P.a[5] = mkKA(p_x + OFF, 0, wv2, 0, p_v + OFF, 0, 0, 0, 0, 64, 64);
    gemm3<false,true,false,false,false,false><<<dim3(192,1,6), 128>>>(P);

    // 5-6. kv partials, reduce + fold wp into M
    kvpart_kernel<<<dim3(48, 2), 512>>>();
    kvm_kernel<<<2, 512>>>(wp1, wp2);

    // 7. emb = x + q @ M   (writes g_emb and emb1/emb2 output regions)
    P.a[0] = mkKA(p_q,       0, p_M,        p_x,       p_emb,       out,       0,0,0, 64, 64);
    P.a[1] = mkKA(p_q + OFF, 0, p_M + 4096, p_x + OFF, p_emb + OFF, out + OFF, 0,0,0, 64, 64);
    for (int i = 2; i < 6; i++) P.a[i] = P.a[0];
    gemm3<false,false,true,false,true,false><<<dim3(192,1,2), 128>>>(P);

    // 8. MLP
    fc_kernel<<<96, 256>>>(fc1w, fc1b, fc2w, fc2b, out + 2*OFF);

    // 9. u = AS @ comb
    P.a[0] = mkKA(AS1, 0, p_comb, 0, p_u,       0, 0, 0, 0, NR, 64);
    P.a[1] = mkKA(AS2, 0, p_comb, 0, p_u + OFF, 0, 0, 0, 0, NR, 64);
    for (int i = 2; i < 6; i++) P.a[i] = P.a[0];
    gemm3<false,false,false,false,false,false><<<dim3(192,1,2), 128>>>(P);

    // 10. recon = spike(u @ w_dec)  (N-tiled)
    P.a[0] = mkKA(p_u, 0, wdec1, 0, out + 3*(size_t)OFF, 0, 0, 0, 0, 64, 3000);
    for (int i = 1; i < 6; i++) P.a[i] = P.a[0];
    gemm3<false,true,false,false,false,true><<<dim3(192,47,1), 128>>>(P);

    P.a[0] = mkKA(p_u + OFF, 0, wdec2, 0, out + 3*(size_t)OFF + (size_t)NR*3000,
                  0, 0, 0, 0, 64, 512);
    for (int i = 1; i < 6; i++) P.a[i] = P.a[0];
    gemm3<false,true,false,false,false,true><<<dim3(192,8,1), 128>>>(P);
}